// round 15
// baseline (speedup 1.0000x reference)
#include <cuda_runtime.h>
#include <cuda_fp16.h>
#include <cstdint>

// ---------------- scratch (static device globals) ---------------------------
// votes layout: [b][n][c(10)][o(16)] halves -> ROW=160 halves per (b,n).
__device__ __half g_votes[256u * 1152u * 160u];  // ~94 MB
__device__ float  g_s[3][256 * 160];             // per-pass s accumulators
// NOTE: g_s starts zero (static init) and is re-zeroed by finish2 each run.

// ---------------- constants -------------------------------------------------
#define NB      256
#define NN      1152
#define NC      10
#define CO      160
#define ROW     160            // halves per (b,n) row
#define GN      16             // n's per votes block
#define NGRP    (NN/GN)        // 72
#define RSPLIT  12             // route chunks per batch
#define RCH     (NN/RSPLIT)    // 96 n per chunk
#define POSE_OFF   0
#define ACT_OFF    40960
#define COUP_OFF   43520

// ---------------- f32x2 helpers (votes GEMM) --------------------------------
typedef unsigned long long u64t;
__device__ __forceinline__ u64t pack2(float lo, float hi) {
    u64t r; asm("mov.b64 %0, {%1, %2};" : "=l"(r) : "f"(lo), "f"(hi)); return r;
}
__device__ __forceinline__ void unpack2(u64t v, float& lo, float& hi) {
    asm("mov.b64 {%0, %1}, %2;" : "=f"(lo), "=f"(hi) : "l"(v));
}
__device__ __forceinline__ u64t fma2(u64t a, u64t b, u64t c) {
    u64t r; asm("fma.rn.f32x2 %0, %1, %2, %3;" : "=l"(r) : "l"(a), "l"(b), "l"(c)); return r;
}
__device__ __forceinline__ void stcs_f32(float* p, float v) {
    asm volatile("st.global.cs.f32 [%0], %1;" :: "l"(p), "f"(v));
}

// squash over a 16-lane o-group (full-warp participation required)
__device__ __forceinline__ float squash16(float s) {
    float sq = s * s;
#pragma unroll
    for (int m = 1; m < 16; m <<= 1)
        sq += __shfl_xor_sync(0xFFFFFFFFu, sq, m, 16);
    float norm = sqrtf(sq + 1e-8f);
    return sq / (1.0f + sq) * (s / norm);
}

// ============================================================================
// Kernel A: votes GEMM, f32x2, fp16 out, fused pass-0 s0 accumulation.
// grid (4 bc, 72 ng): block = 16 n x 64 b, 320 threads.
// W staged in smem as pre-duplicated (w,w) f32x2 pairs -> mainloop per i is
// 2 LDS.128 (w-pairs) + 2 LDS.128 (p-pairs) + 16 FFMA2, no pack MOVs.
// ============================================================================
__global__ __launch_bounds__(320, 2) void votes_kernel(
    const float* __restrict__ P, const float* __restrict__ W)
{
    const int bc  = blockIdx.x;     // 0..3 -> 64 b
    const int ng  = blockIdx.y;     // 0..71 -> 16 n
    const int t   = threadIdx.x;
    const int tco = t % 40;
    const int tb  = t / 40;
    const int co4 = tco * 4;
    const int b8  = tb * 8;

    __shared__ u64t  wt2[16][164];  // [i][co] duplicated pairs, padded
    __shared__ float spt[16][68];   // [i][b], rows 272B (16B-aligned)

    u64t s0acc[16];
#pragma unroll
    for (int j = 0; j < 16; j++) s0acc[j] = 0ull;

    for (int g = 0; g < GN; g++) {
        const int n = ng * GN + g;

        __syncthreads();

        {
            const float4* Wn = (const float4*)(W + (size_t)n * (CO * 16));
#pragma unroll
            for (int r = 0; r < 2; r++) {
                int f = t + r * 320;
                float4 x = Wn[f];
                int co = f >> 2, i0 = (f & 3) * 4;
                wt2[i0 + 0][co] = pack2(x.x, x.x);
                wt2[i0 + 1][co] = pack2(x.y, x.y);
                wt2[i0 + 2][co] = pack2(x.z, x.z);
                wt2[i0 + 3][co] = pack2(x.w, x.w);
            }
        }
        if (t < 256) {
            int b = t >> 2, i0 = (t & 3) * 4;
            float4 x = *(const float4*)(P + ((size_t)(bc * 64 + b) * NN + n) * 16 + i0);
            spt[i0 + 0][b] = x.x; spt[i0 + 1][b] = x.y;
            spt[i0 + 2][b] = x.z; spt[i0 + 3][b] = x.w;
        }
        __syncthreads();

        u64t acc[16];
#pragma unroll
        for (int j = 0; j < 16; j++) acc[j] = 0ull;

#pragma unroll
        for (int i = 0; i < 16; i++) {
            // 4 duplicated w-pairs: 32B contiguous -> 2 LDS.128
            union { uint4 q; u64t u[2]; } wa, wb, pa, pb;
            const uint4* wp = (const uint4*)&wt2[i][co4];
            wa.q = wp[0]; wb.q = wp[1];
            const uint4* pp = (const uint4*)&spt[i][b8];
            pa.q = pp[0]; pb.q = pp[1];
            const u64t ww0 = wa.u[0], ww1 = wa.u[1];
            const u64t ww2 = wb.u[0], ww3 = wb.u[1];
            const u64t p0 = pa.u[0], p1 = pa.u[1];
            const u64t p2 = pb.u[0], p3 = pb.u[1];
            acc[0]  = fma2(ww0, p0, acc[0]);  acc[1]  = fma2(ww0, p1, acc[1]);
            acc[2]  = fma2(ww0, p2, acc[2]);  acc[3]  = fma2(ww0, p3, acc[3]);
            acc[4]  = fma2(ww1, p0, acc[4]);  acc[5]  = fma2(ww1, p1, acc[5]);
            acc[6]  = fma2(ww1, p2, acc[6]);  acc[7]  = fma2(ww1, p3, acc[7]);
            acc[8]  = fma2(ww2, p0, acc[8]);  acc[9]  = fma2(ww2, p1, acc[9]);
            acc[10] = fma2(ww2, p2, acc[10]); acc[11] = fma2(ww2, p3, acc[11]);
            acc[12] = fma2(ww3, p0, acc[12]); acc[13] = fma2(ww3, p1, acc[13]);
            acc[14] = fma2(ww3, p2, acc[14]); acc[15] = fma2(ww3, p3, acc[15]);
        }

        // accumulate s0 and store votes (8 b x 4 co per thread)
#pragma unroll
        for (int k = 0; k < 4; k++) {
            float lo[4], hi[4];
#pragma unroll
            for (int j = 0; j < 4; j++) {
                u64t a = acc[j * 4 + k];
                s0acc[j * 4 + k] = fma2(pack2(1.f, 1.f), a, s0acc[j * 4 + k]);
                unpack2(a, lo[j], hi[j]);
            }
            union { __half2 h[2]; u64t u; } pk;
            pk.h[0] = __floats2half2_rn(lo[0], lo[1]);
            pk.h[1] = __floats2half2_rn(lo[2], lo[3]);
            *(u64t*)(g_votes + ((size_t)(bc * 64 + b8 + 2*k) * NN + n) * ROW + co4) = pk.u;
            pk.h[0] = __floats2half2_rn(hi[0], hi[1]);
            pk.h[1] = __floats2half2_rn(hi[2], hi[3]);
            *(u64t*)(g_votes + ((size_t)(bc * 64 + b8 + 2*k + 1) * NN + n) * ROW + co4) = pk.u;
        }
    }

    // fused pass-0 atomics (32 per thread)
#pragma unroll
    for (int k = 0; k < 4; k++) {
#pragma unroll
        for (int j = 0; j < 4; j++) {
            float lo, hi;
            unpack2(s0acc[j * 4 + k], lo, hi);
            atomicAdd(&g_s[0][(bc * 64 + b8 + 2*k)     * CO + co4 + j], 0.1f * lo);
            atomicAdd(&g_s[0][(bc * 64 + b8 + 2*k + 1) * CO + co4 + j], 0.1f * hi);
        }
    }
}

// ============================================================================
// Kernel B (R13): routing pass over 96 n's. grid (256 b, 12 chunks),
// 256 threads = 16 n-slots x 16 c-lanes (c<10 active). Half2 datapath.
// ============================================================================
template <int PASS, int REV>
__global__ __launch_bounds__(256, 7) void route_kernel(
    const float* __restrict__ bias, float* __restrict__ out)
{
    const int b     = blockIdx.x;
    const int chunk = REV ? (RSPLIT - 1 - (int)blockIdx.y) : (int)blockIdx.y;
    const int t     = threadIdx.x;
    const int nl    = t >> 4;
    const int cl    = t & 15;

    __shared__ float svsum[160];
    __shared__ float sred[8 * 160];
    __shared__ float ccs[10][97];

    // recompute vsum from global s (pass1: v0; pass2: v0+v1)
    if (t < 160) {
        float bs = bias[t];
        float v = squash16(g_s[0][b * CO + t] + bs);
        if (PASS == 2)
            v += squash16(g_s[1][b * CO + t] + bs);
        svsum[t] = v;
    }
    __syncthreads();

    const bool act = (cl < 10);

    __half2 vsh[8];
    {
        const float* src = svsum + (act ? cl : 0) * 16;
#pragma unroll
        for (int j = 0; j < 8; j++)
            vsh[j] = __floats2half2_rn(src[2*j], src[2*j + 1]);
    }

    __half2 sacc[8];
#pragma unroll
    for (int j = 0; j < 8; j++) sacc[j] = __float2half2_rn(0.f);

    const __half* base = g_votes + ((size_t)b * NN + (size_t)chunk * RCH) * ROW;
    const int coff = (act ? cl : 0) * 16;

#pragma unroll
    for (int k = 0; k < RCH / 16; k++) {
        const int nloc = k * 16 + nl;
        __half2 vv[8];
        float lg = 0.f;
        if (act) {
            const uint4* rp = (const uint4*)(base + (size_t)nloc * ROW + coff);
            uint4 q0 = rp[0];
            uint4 q1 = rp[1];
            vv[0] = *(__half2*)&q0.x; vv[1] = *(__half2*)&q0.y;
            vv[2] = *(__half2*)&q0.z; vv[3] = *(__half2*)&q0.w;
            vv[4] = *(__half2*)&q1.x; vv[5] = *(__half2*)&q1.y;
            vv[6] = *(__half2*)&q1.z; vv[7] = *(__half2*)&q1.w;

            __half2 la = __hmul2(vv[0], vsh[0]);
            __half2 lb = __hmul2(vv[1], vsh[1]);
            la = __hfma2(vv[2], vsh[2], la);
            lb = __hfma2(vv[3], vsh[3], lb);
            la = __hfma2(vv[4], vsh[4], la);
            lb = __hfma2(vv[5], vsh[5], lb);
            la = __hfma2(vv[6], vsh[6], la);
            lb = __hfma2(vv[7], vsh[7], lb);
            float2 fa = __half22float2(la);
            float2 fb = __half22float2(lb);
            lg = (fa.x + fa.y) + (fb.x + fb.y);
        }

        float e = act ? __expf(lg) : 0.f;
        float den = e;
#pragma unroll
        for (int m = 1; m < 16; m <<= 1)
            den += __shfl_xor_sync(0xFFFFFFFFu, den, m, 16);
        float cc = __fdividef(e, den);

        if (act) {
            __half2 cch = __float2half2_rn(cc);
#pragma unroll
            for (int j = 0; j < 8; j++) sacc[j] = __hfma2(cch, vv[j], sacc[j]);
            if (PASS == 2) ccs[cl][nloc] = cc;
        }
    }

    // ---- convert sacc to fp32, fold warp's 2 n-slots, reduce, atomics ----
    float sf[16];
#pragma unroll
    for (int j = 0; j < 8; j++) {
        float2 f = __half22float2(sacc[j]);
        sf[2*j] = f.x; sf[2*j + 1] = f.y;
    }
#pragma unroll
    for (int o = 0; o < 16; o++)
        sf[o] += __shfl_xor_sync(0xFFFFFFFFu, sf[o], 16, 32);

    const int w = t >> 5;
    if ((t & 16) == 0 && act) {
        float* dst = sred + w * 160 + cl * 16;
#pragma unroll
        for (int j = 0; j < 4; j++)
            *(float4*)(dst + j * 4) =
                make_float4(sf[j*4], sf[j*4+1], sf[j*4+2], sf[j*4+3]);
    }
    __syncthreads();

    if (t < 160) {
        float s = 0.f;
#pragma unroll
        for (int w2 = 0; w2 < 8; w2++) s += sred[w2 * 160 + t];
        atomicAdd(&g_s[PASS][b * CO + t], s);
    }

    if (PASS == 2) {
        for (int idx = t; idx < NC * RCH; idx += 256) {
            int c = idx / RCH, nn2 = idx % RCH;
            stcs_f32(out + COUP_OFF + (size_t)b * (NC * NN) + (size_t)c * NN
                     + (size_t)chunk * RCH + nn2, ccs[c][nn2]);
        }
    }
}

// ============================================================================
// finish2: final outputs from complete s2, then zero g_s for the next replay
// (replaces the init kernel; state is deterministic across graph replays).
// ============================================================================
__global__ __launch_bounds__(160) void finish2_kernel(
    const float* __restrict__ bias, float* __restrict__ out)
{
    const int b = blockIdx.x;
    const int t = threadIdx.x;
    const int c = t >> 4, o = t & 15;

    float v = squash16(g_s[2][b * CO + t] + bias[t]);

    // zero accumulators for the next run
    g_s[0][b * CO + t] = 0.f;
    g_s[1][b * CO + t] = 0.f;
    g_s[2][b * CO + t] = 0.f;

    stcs_f32(out + POSE_OFF + (size_t)b * CO + t, v);
    float vsq = v * v;
#pragma unroll
    for (int m = 1; m < 16; m <<= 1)
        vsq += __shfl_xor_sync(0xFFFFFFFFu, vsq, m, 16);
    if (o == 0) stcs_f32(out + ACT_OFF + b * NC + c, sqrtf(vsq + 1e-8f));
}

// ============================================================================
extern "C" void kernel_launch(void* const* d_in, const int* in_sizes, int n_in,
                              void* d_out, int out_size)
{
    const float* P    = (const float*)d_in[0];  // (256,32,6,6,16,1)
    const float* W    = (const float*)d_in[2];  // (32,6,6,10,16,16)
    const float* bias = (const float*)d_in[3];  // (10,1,1,16,1)
    float* out = (float*)d_out;

    votes_kernel<<<dim3(4, NGRP), 320>>>(P, W);
    route_kernel<1, 1><<<dim3(NB, RSPLIT), 256>>>(bias, out);
    route_kernel<2, 0><<<dim3(NB, RSPLIT), 256>>>(bias, out);
    finish2_kernel<<<NB, 160>>>(bias, out);
}

// round 16
// speedup vs baseline: 1.3168x; 1.3168x over previous
#include <cuda_runtime.h>
#include <cuda_fp16.h>
#include <cstdint>

// ---------------- scratch (static device globals) ---------------------------
// votes layout: [b][n][c(10)][o(16)] halves -> ROW=160 halves per (b,n).
__device__ __half g_votes[256u * 1152u * 160u];  // ~94 MB
__device__ float  g_s[3][256 * 160];             // per-pass s accumulators
// g_s starts zero (static init) and is re-zeroed by finish2 every run, so
// state is deterministic across the harness's correctness run and replays.

// ---------------- constants -------------------------------------------------
#define NB      256
#define NN      1152
#define NC      10
#define CO      160
#define ROW     160            // halves per (b,n) row
#define GN      16             // n's per votes block
#define NGRP    (NN/GN)        // 72
#define RSPLIT  12             // route chunks per batch
#define RCH     (NN/RSPLIT)    // 96 n per chunk
#define POSE_OFF   0
#define ACT_OFF    40960
#define COUP_OFF   43520

// ---------------- f32x2 helpers (votes GEMM) --------------------------------
typedef unsigned long long u64t;
__device__ __forceinline__ u64t pack2(float lo, float hi) {
    u64t r; asm("mov.b64 %0, {%1, %2};" : "=l"(r) : "f"(lo), "f"(hi)); return r;
}
__device__ __forceinline__ void unpack2(u64t v, float& lo, float& hi) {
    asm("mov.b64 {%0, %1}, %2;" : "=f"(lo), "=f"(hi) : "l"(v));
}
__device__ __forceinline__ u64t fma2(u64t a, u64t b, u64t c) {
    u64t r; asm("fma.rn.f32x2 %0, %1, %2, %3;" : "=l"(r) : "l"(a), "l"(b), "l"(c)); return r;
}
__device__ __forceinline__ void stcs_f32(float* p, float v) {
    asm volatile("st.global.cs.f32 [%0], %1;" :: "l"(p), "f"(v));
}

// squash over a 16-lane o-group (full-warp participation required)
__device__ __forceinline__ float squash16(float s) {
    float sq = s * s;
#pragma unroll
    for (int m = 1; m < 16; m <<= 1)
        sq += __shfl_xor_sync(0xFFFFFFFFu, sq, m, 16);
    float norm = sqrtf(sq + 1e-8f);
    return sq / (1.0f + sq) * (s / norm);
}

// ============================================================================
// Kernel A (R8, measured-best): votes GEMM, f32x2, fp16 out, fused pass-0.
// grid (4 bc, 72 ng): block = 16 n x 64 b, 320 threads.
// ============================================================================
__global__ __launch_bounds__(320, 2) void votes_kernel(
    const float* __restrict__ P, const float* __restrict__ W)
{
    const int bc  = blockIdx.x;     // 0..3 -> 64 b
    const int ng  = blockIdx.y;     // 0..71 -> 16 n
    const int t   = threadIdx.x;
    const int tco = t % 40;
    const int tb  = t / 40;
    const int co4 = tco * 4;
    const int b8  = tb * 8;

    __shared__ float wt[16][164];   // [i][co], padded
    __shared__ float spt[16][66];   // [i][b], padded

    u64t s0acc[16];
#pragma unroll
    for (int j = 0; j < 16; j++) s0acc[j] = 0ull;

    for (int g = 0; g < GN; g++) {
        const int n = ng * GN + g;

        __syncthreads();

        {
            const float4* Wn = (const float4*)(W + (size_t)n * (CO * 16));
#pragma unroll
            for (int r = 0; r < 2; r++) {
                int f = t + r * 320;
                float4 x = Wn[f];
                int co = f >> 2, i0 = (f & 3) * 4;
                wt[i0 + 0][co] = x.x; wt[i0 + 1][co] = x.y;
                wt[i0 + 2][co] = x.z; wt[i0 + 3][co] = x.w;
            }
        }
        if (t < 256) {
            int b = t >> 2, i0 = (t & 3) * 4;
            float4 x = *(const float4*)(P + ((size_t)(bc * 64 + b) * NN + n) * 16 + i0);
            spt[i0 + 0][b] = x.x; spt[i0 + 1][b] = x.y;
            spt[i0 + 2][b] = x.z; spt[i0 + 3][b] = x.w;
        }
        __syncthreads();

        u64t acc[16];
#pragma unroll
        for (int j = 0; j < 16; j++) acc[j] = 0ull;

#pragma unroll
        for (int i = 0; i < 16; i++) {
            float4 w4 = *(const float4*)&wt[i][co4];
            u64t p0 = *(const u64t*)&spt[i][b8 + 0];
            u64t p1 = *(const u64t*)&spt[i][b8 + 2];
            u64t p2 = *(const u64t*)&spt[i][b8 + 4];
            u64t p3 = *(const u64t*)&spt[i][b8 + 6];
            u64t ww;
            ww = pack2(w4.x, w4.x);
            acc[0]  = fma2(ww, p0, acc[0]);  acc[1]  = fma2(ww, p1, acc[1]);
            acc[2]  = fma2(ww, p2, acc[2]);  acc[3]  = fma2(ww, p3, acc[3]);
            ww = pack2(w4.y, w4.y);
            acc[4]  = fma2(ww, p0, acc[4]);  acc[5]  = fma2(ww, p1, acc[5]);
            acc[6]  = fma2(ww, p2, acc[6]);  acc[7]  = fma2(ww, p3, acc[7]);
            ww = pack2(w4.z, w4.z);
            acc[8]  = fma2(ww, p0, acc[8]);  acc[9]  = fma2(ww, p1, acc[9]);
            acc[10] = fma2(ww, p2, acc[10]); acc[11] = fma2(ww, p3, acc[11]);
            ww = pack2(w4.w, w4.w);
            acc[12] = fma2(ww, p0, acc[12]); acc[13] = fma2(ww, p1, acc[13]);
            acc[14] = fma2(ww, p2, acc[14]); acc[15] = fma2(ww, p3, acc[15]);
        }

        // accumulate s0 and store votes (8 b x 4 co per thread)
#pragma unroll
        for (int k = 0; k < 4; k++) {
            float lo[4], hi[4];
#pragma unroll
            for (int j = 0; j < 4; j++) {
                u64t a = acc[j * 4 + k];
                s0acc[j * 4 + k] = fma2(pack2(1.f, 1.f), a, s0acc[j * 4 + k]);
                unpack2(a, lo[j], hi[j]);
            }
            union { __half2 h[2]; u64t u; } pk;
            pk.h[0] = __floats2half2_rn(lo[0], lo[1]);
            pk.h[1] = __floats2half2_rn(lo[2], lo[3]);
            *(u64t*)(g_votes + ((size_t)(bc * 64 + b8 + 2*k) * NN + n) * ROW + co4) = pk.u;
            pk.h[0] = __floats2half2_rn(hi[0], hi[1]);
            pk.h[1] = __floats2half2_rn(hi[2], hi[3]);
            *(u64t*)(g_votes + ((size_t)(bc * 64 + b8 + 2*k + 1) * NN + n) * ROW + co4) = pk.u;
        }
    }

    // fused pass-0 atomics (32 per thread)
#pragma unroll
    for (int k = 0; k < 4; k++) {
#pragma unroll
        for (int j = 0; j < 4; j++) {
            float lo, hi;
            unpack2(s0acc[j * 4 + k], lo, hi);
            atomicAdd(&g_s[0][(bc * 64 + b8 + 2*k)     * CO + co4 + j], 0.1f * lo);
            atomicAdd(&g_s[0][(bc * 64 + b8 + 2*k + 1) * CO + co4 + j], 0.1f * hi);
        }
    }
}

// ============================================================================
// Kernel B (R8, measured-best): routing pass over 96 n's.
// grid (256 b, 12 chunks), 256 threads = 16 n-slots x 16 c-lanes (c<10
// active). Half2 datapath, two 16B LDGs per (n,c) iteration.
// ============================================================================
template <int PASS, int REV>
__global__ __launch_bounds__(256) void route_kernel(
    const float* __restrict__ bias, float* __restrict__ out)
{
    const int b     = blockIdx.x;
    const int chunk = REV ? (RSPLIT - 1 - (int)blockIdx.y) : (int)blockIdx.y;
    const int t     = threadIdx.x;
    const int nl    = t >> 4;
    const int cl    = t & 15;

    __shared__ float svsum[160];
    __shared__ float sred[8 * 160];
    __shared__ float ccs[10][97];

    // recompute vsum from global s (pass1: v0; pass2: v0+v1)
    if (t < 160) {
        float bs = bias[t];
        float v = squash16(g_s[0][b * CO + t] + bs);
        if (PASS == 2)
            v += squash16(g_s[1][b * CO + t] + bs);
        svsum[t] = v;
    }
    __syncthreads();

    const bool act = (cl < 10);

    __half2 vsh[8];
    {
        const float* src = svsum + (act ? cl : 0) * 16;
#pragma unroll
        for (int j = 0; j < 8; j++)
            vsh[j] = __floats2half2_rn(src[2*j], src[2*j + 1]);
    }

    __half2 sacc[8];
#pragma unroll
    for (int j = 0; j < 8; j++) sacc[j] = __float2half2_rn(0.f);

    const __half* base = g_votes + ((size_t)b * NN + (size_t)chunk * RCH) * ROW;
    const int coff = (act ? cl : 0) * 16;

#pragma unroll
    for (int k = 0; k < RCH / 16; k++) {
        const int nloc = k * 16 + nl;
        __half2 vv[8];
        float lg = 0.f;
        if (act) {
            const uint4* rp = (const uint4*)(base + (size_t)nloc * ROW + coff);
            uint4 q0 = rp[0];
            uint4 q1 = rp[1];
            vv[0] = *(__half2*)&q0.x; vv[1] = *(__half2*)&q0.y;
            vv[2] = *(__half2*)&q0.z; vv[3] = *(__half2*)&q0.w;
            vv[4] = *(__half2*)&q1.x; vv[5] = *(__half2*)&q1.y;
            vv[6] = *(__half2*)&q1.z; vv[7] = *(__half2*)&q1.w;

            __half2 la = __hmul2(vv[0], vsh[0]);
            __half2 lb = __hmul2(vv[1], vsh[1]);
            la = __hfma2(vv[2], vsh[2], la);
            lb = __hfma2(vv[3], vsh[3], lb);
            la = __hfma2(vv[4], vsh[4], la);
            lb = __hfma2(vv[5], vsh[5], lb);
            la = __hfma2(vv[6], vsh[6], la);
            lb = __hfma2(vv[7], vsh[7], lb);
            float2 fa = __half22float2(la);
            float2 fb = __half22float2(lb);
            lg = (fa.x + fa.y) + (fb.x + fb.y);
        }

        float e = act ? __expf(lg) : 0.f;
        float den = e;
#pragma unroll
        for (int m = 1; m < 16; m <<= 1)
            den += __shfl_xor_sync(0xFFFFFFFFu, den, m, 16);
        float cc = __fdividef(e, den);

        if (act) {
            __half2 cch = __float2half2_rn(cc);
#pragma unroll
            for (int j = 0; j < 8; j++) sacc[j] = __hfma2(cch, vv[j], sacc[j]);
            if (PASS == 2) ccs[cl][nloc] = cc;
        }
    }

    // ---- convert sacc to fp32, fold warp's 2 n-slots, reduce, atomics ----
    float sf[16];
#pragma unroll
    for (int j = 0; j < 8; j++) {
        float2 f = __half22float2(sacc[j]);
        sf[2*j] = f.x; sf[2*j + 1] = f.y;
    }
#pragma unroll
    for (int o = 0; o < 16; o++)
        sf[o] += __shfl_xor_sync(0xFFFFFFFFu, sf[o], 16, 32);

    const int w = t >> 5;
    if ((t & 16) == 0 && act) {
        float* dst = sred + w * 160 + cl * 16;
#pragma unroll
        for (int j = 0; j < 4; j++)
            *(float4*)(dst + j * 4) =
                make_float4(sf[j*4], sf[j*4+1], sf[j*4+2], sf[j*4+3]);
    }
    __syncthreads();

    if (t < 160) {
        float s = 0.f;
#pragma unroll
        for (int w2 = 0; w2 < 8; w2++) s += sred[w2 * 160 + t];
        atomicAdd(&g_s[PASS][b * CO + t], s);
    }

    if (PASS == 2) {
        for (int idx = t; idx < NC * RCH; idx += 256) {
            int c = idx / RCH, nn2 = idx % RCH;
            stcs_f32(out + COUP_OFF + (size_t)b * (NC * NN) + (size_t)c * NN
                     + (size_t)chunk * RCH + nn2, ccs[c][nn2]);
        }
    }
}

// ============================================================================
// finish2: final outputs from complete s2, then zero g_s for the next replay
// (replaces the init kernel; deterministic across graph replays).
// ============================================================================
__global__ __launch_bounds__(160) void finish2_kernel(
    const float* __restrict__ bias, float* __restrict__ out)
{
    const int b = blockIdx.x;
    const int t = threadIdx.x;
    const int c = t >> 4, o = t & 15;

    float v = squash16(g_s[2][b * CO + t] + bias[t]);

    // zero accumulators for the next run
    g_s[0][b * CO + t] = 0.f;
    g_s[1][b * CO + t] = 0.f;
    g_s[2][b * CO + t] = 0.f;

    stcs_f32(out + POSE_OFF + (size_t)b * CO + t, v);
    float vsq = v * v;
#pragma unroll
    for (int m = 1; m < 16; m <<= 1)
        vsq += __shfl_xor_sync(0xFFFFFFFFu, vsq, m, 16);
    if (o == 0) stcs_f32(out + ACT_OFF + b * NC + c, sqrtf(vsq + 1e-8f));
}

// ============================================================================
extern "C" void kernel_launch(void* const* d_in, const int* in_sizes, int n_in,
                              void* d_out, int out_size)
{
    const float* P    = (const float*)d_in[0];  // (256,32,6,6,16,1)
    const float* W    = (const float*)d_in[2];  // (32,6,6,10,16,16)
    const float* bias = (const float*)d_in[3];  // (10,1,1,16,1)
    float* out = (float*)d_out;

    votes_kernel<<<dim3(4, NGRP), 320>>>(P, W);
    route_kernel<1, 1><<<dim3(NB, RSPLIT), 256>>>(bias, out);
    route_kernel<2, 0><<<dim3(NB, RSPLIT), 256>>>(bias, out);
    finish2_kernel<<<NB, 160>>>(bias, out);
}